// round 2
// baseline (speedup 1.0000x reference)
#include <cuda_runtime.h>
#include <cstdint>

#define BSZ 4
#define CIN 96
#define LL  4096
#define DI  192
#define NS  16

// ---------------- scratch (static device globals; no allocation) ----------------
__device__ float  g_upre[2][BSZ][DI][LL];   // in-proj u part (pre conv)
__device__ float  g_g   [2][BSZ][DI][LL];   // silu(z)
__device__ float  g_u   [2][BSZ][DI][LL];   // post conv+silu u
__device__ float2 g_td  [2][BSZ][DI][LL];   // (delta, delta*u)
__device__ float2 g_gb  [2][BSZ][DI][LL];   // (silu(z), u*D*silu(z))
__device__ float  g_dt6 [2][BSZ][LL][8];    // dt low-rank (6, padded 8)
__device__ float  g_bc  [2][BSZ][LL][2*NS]; // Bm(16) then Cm(16)
__device__ float  g_y   [2][BSZ][DI][LL];   // scan output (gated)
__device__ float  g_fin [BSZ][CIN][LL];     // fused pre-BN output
__device__ float  g_wc  [2][DI][128];       // combined out_W@fuse_W (o padded to 128)

__device__ __forceinline__ float fsilu(float x){ return x / (1.f + __expf(-x)); }
__device__ __forceinline__ float fex2(float x){ float y; asm("ex2.approx.ftz.f32 %0, %1;" : "=f"(y) : "f"(x)); return y; }

// ---------------- K0: combined projection weights ----------------
// wc[dir][d][o] = sum_c outW_dir[d][c] * fuse_W[o][dir*96 + c]
__global__ void k_wcomb(const float* __restrict__ foW, const float* __restrict__ boW,
                        const float* __restrict__ fuW){
    int d = blockIdx.x, dir = blockIdx.y;
    int o = threadIdx.x; // 0..127
    float acc = 0.f;
    if (o < CIN){
        const float* oW = dir ? boW : foW;
        #pragma unroll 8
        for (int c = 0; c < CIN; c++)
            acc += oW[d*CIN + c] * fuW[o*(2*CIN) + dir*CIN + c];
    }
    g_wc[dir][d][o] = acc;
}

// ---------------- K1: in-projection GEMM ----------------
// out[j][l] = sum_c x[b][c][l(dir)] * in_W[c][j],  j<384 (u | z)
__global__ void __launch_bounds__(256) k_inproj(const float* __restrict__ x,
                                                const float* __restrict__ fW,
                                                const float* __restrict__ bW){
    int lt = blockIdx.x*64, jt = blockIdx.y*128;
    int dir = blockIdx.z >> 2, b = blockIdx.z & 3;
    const float* W = dir ? bW : fW;
    __shared__ float Ws[48][128];
    __shared__ float Xs[48][64];
    int tid = threadIdx.x;
    int jb = (tid & 31)*4, lb = (tid >> 5)*8;
    float acc[8][4];
    #pragma unroll
    for (int i = 0; i < 8; i++)
        #pragma unroll
        for (int j = 0; j < 4; j++) acc[i][j] = 0.f;

    for (int cc = 0; cc < 96; cc += 48){
        for (int idx = tid; idx < 48*32; idx += 256){
            int c = idx >> 5, q = idx & 31;
            *(float4*)&Ws[c][q*4] = *(const float4*)&W[(cc+c)*384 + jt + q*4];
        }
        for (int idx = tid; idx < 48*64; idx += 256){
            int c = idx >> 6, i = idx & 63;
            int li = lt + i; if (dir) li = LL-1-li;
            Xs[c][i] = x[((b*CIN)+(cc+c))*LL + li];
        }
        __syncthreads();
        #pragma unroll 4
        for (int c = 0; c < 48; c++){
            float4 wv = *(float4*)&Ws[c][jb];
            float4 x0 = *(float4*)&Xs[c][lb];
            float4 x1 = *(float4*)&Xs[c][lb+4];
            float xv[8] = {x0.x,x0.y,x0.z,x0.w,x1.x,x1.y,x1.z,x1.w};
            float wr[4] = {wv.x,wv.y,wv.z,wv.w};
            #pragma unroll
            for (int i = 0; i < 8; i++)
                #pragma unroll
                for (int j = 0; j < 4; j++) acc[i][j] += xv[i]*wr[j];
        }
        __syncthreads();
    }
    #pragma unroll
    for (int i = 0; i < 8; i++){
        int l = lt + lb + i;
        #pragma unroll
        for (int j = 0; j < 4; j++){
            int jj = jt + jb + j;
            float v = acc[i][j];
            if (jj < DI) g_upre[dir][b][jj][l] = v;
            else         g_g[dir][b][jj-DI][l] = fsilu(v);
        }
    }
}

// ---------------- K2: causal depthwise conv(K=4) + bias + silu ----------------
__global__ void __launch_bounds__(128) k_conv(const float* __restrict__ fw, const float* __restrict__ fb,
                                              const float* __restrict__ bw, const float* __restrict__ bb){
    int dir = blockIdx.z >> 2, b = blockIdx.z & 3;
    int d = blockIdx.y;
    int l = blockIdx.x*128 + threadIdx.x;
    const float* cw = (dir ? bw : fw) + d*4;
    float bias = (dir ? bb : fb)[d];
    const float* up = &g_upre[dir][b][d][0];
    float v = up[l]*cw[3] + bias;
    if (l >= 1) v += up[l-1]*cw[2];
    if (l >= 2) v += up[l-2]*cw[1];
    if (l >= 3) v += up[l-3]*cw[0];
    g_u[dir][b][d][l] = fsilu(v);
}

// ---------------- K3: x-projection GEMM (192 -> 38, padded to 40) ----------------
__global__ void __launch_bounds__(256) k_xproj(const float* __restrict__ fX, const float* __restrict__ bX){
    int lt = blockIdx.x*256;
    int b = blockIdx.y, dir = blockIdx.z;
    const float* xW = dir ? bX : fX; // (192 x 38)
    __shared__ float Ws[192][40];
    __shared__ float Us[16][256];
    int tid = threadIdx.x;
    for (int idx = tid; idx < 192*40; idx += 256){
        int d = idx/40, j = idx - d*40;
        Ws[d][j] = (j < 38) ? xW[d*38 + j] : 0.f;
    }
    int jb = (tid & 7)*5, lb = (tid >> 3)*8;
    float acc[5][8];
    #pragma unroll
    for (int i = 0; i < 5; i++)
        #pragma unroll
        for (int j = 0; j < 8; j++) acc[i][j] = 0.f;

    for (int c0 = 0; c0 < 192; c0 += 16){
        __syncthreads();
        for (int idx = tid; idx < 16*256; idx += 256){
            int c = idx >> 8, i = idx & 255;
            Us[c][i] = g_u[dir][b][c0+c][lt+i];
        }
        __syncthreads();
        #pragma unroll 4
        for (int c = 0; c < 16; c++){
            float w[5];
            #pragma unroll
            for (int j = 0; j < 5; j++) w[j] = Ws[c0+c][jb+j];
            float4 u0 = *(float4*)&Us[c][lb];
            float4 u1 = *(float4*)&Us[c][lb+4];
            float uv[8] = {u0.x,u0.y,u0.z,u0.w,u1.x,u1.y,u1.z,u1.w};
            #pragma unroll
            for (int j = 0; j < 5; j++)
                #pragma unroll
                for (int i = 0; i < 8; i++) acc[j][i] += w[j]*uv[i];
        }
    }
    #pragma unroll
    for (int j = 0; j < 5; j++){
        int jj = jb + j;
        #pragma unroll
        for (int i = 0; i < 8; i++){
            int l = lt + lb + i;
            float v = acc[j][i];
            if (jj < 6)       g_dt6[dir][b][l][jj] = v;
            else if (jj < 38) g_bc[dir][b][l][jj-6] = v;
        }
    }
}

// ---------------- K4: delta = softplus(dt@dt_W + b), pack scan inputs ----------------
__global__ void __launch_bounds__(256) k_delta(const float* __restrict__ fdtW, const float* __restrict__ fdtb,
                                               const float* __restrict__ fD,
                                               const float* __restrict__ bdtW, const float* __restrict__ bdtb,
                                               const float* __restrict__ bD){
    int dir = blockIdx.z, b = blockIdx.y;
    int li = blockIdx.x*128 + (threadIdx.x & 127);
    int du = threadIdx.x >> 7;
    const float* dtW = dir ? bdtW : fdtW;
    const float* dtb = dir ? bdtb : fdtb;
    const float* Dv  = dir ? bD   : fD;
    float dt[6];
    #pragma unroll
    for (int r = 0; r < 6; r++) dt[r] = g_dt6[dir][b][li][r];
    for (int d = du; d < DI; d += 2){
        float acc = dtb[d];
        #pragma unroll
        for (int r = 0; r < 6; r++) acc += dt[r]*dtW[r*DI + d];
        float delta = (acc > 15.f) ? acc : log1pf(__expf(acc));
        float u = g_u[dir][b][d][li];
        float g = g_g[dir][b][d][li];
        g_td[dir][b][d][li] = make_float2(delta, delta*u);
        g_gb[dir][b][d][li] = make_float2(g, u*Dv[d]*g);
    }
}

// ---------------- K5: selective scan (warp = 2 channels x 16 states) ----------------
__global__ void __launch_bounds__(32) k_scan(const float* __restrict__ fA, const float* __restrict__ bA){
    int d = blockIdx.x*2 + (threadIdx.x >> 4);
    int b = blockIdx.y, dir = blockIdx.z;
    int n = threadIdx.x & 15;
    const float* Alog = dir ? bA : fA;
    float a2 = -__expf(Alog[d*NS + n]) * 1.4426950408889634f; // A * log2(e)
    const float2* td = &g_td[dir][b][d][0];
    const float2* gb = &g_gb[dir][b][d][0];
    const float*  bc = &g_bc[dir][b][0][0];
    float* yo = &g_y[dir][b][d][0];
    float h = 0.f;
    #pragma unroll 4
    for (int l = 0; l < LL; l++){
        float2 t = td[l];
        float Bm = bc[l*32 + n];
        float Cm = bc[l*32 + 16 + n];
        float2 G = gb[l];
        float dA = fex2(t.x * a2);          // exp(delta*A)
        h = fmaf(dA, h, t.y*Bm);            // h = dA*h + delta*u*Bm
        float p = h*Cm;
        p += __shfl_xor_sync(0xffffffffu, p, 1);
        p += __shfl_xor_sync(0xffffffffu, p, 2);
        p += __shfl_xor_sync(0xffffffffu, p, 4);
        p += __shfl_xor_sync(0xffffffffu, p, 8);
        if (n == 0) yo[l] = fmaf(p, G.x, G.y); // (sum + u*D)*silu(z)
    }
}

// ---------------- K6: combined out-proj + fuse GEMM ----------------
// fin[b][o][l] = sum_dir sum_d y[dir][b][d][l(dir)] * wc[dir][d][o] + fuse_b[o]
__global__ void __launch_bounds__(256) k_fuse(const float* __restrict__ fuseb){
    int lt = blockIdx.x*64, b = blockIdx.y;
    __shared__ float Ws[32][128];
    __shared__ float Ys[32][64];
    int tid = threadIdx.x;
    int jb = (tid & 31)*4, lb = (tid >> 5)*8;
    float acc[8][4];
    #pragma unroll
    for (int i = 0; i < 8; i++)
        #pragma unroll
        for (int j = 0; j < 4; j++) acc[i][j] = 0.f;

    for (int dir = 0; dir < 2; dir++){
        for (int c0 = 0; c0 < DI; c0 += 32){
            __syncthreads();
            for (int idx = tid; idx < 32*32; idx += 256){
                int c = idx >> 5, q = idx & 31;
                *(float4*)&Ws[c][q*4] = *(const float4*)&g_wc[dir][c0+c][q*4];
            }
            for (int idx = tid; idx < 32*64; idx += 256){
                int c = idx >> 6, i = idx & 63;
                int li = lt + i; if (dir) li = LL-1-li;
                Ys[c][i] = g_y[dir][b][c0+c][li];
            }
            __syncthreads();
            #pragma unroll 4
            for (int c = 0; c < 32; c++){
                float4 wv = *(float4*)&Ws[c][jb];
                float4 y0 = *(float4*)&Ys[c][lb];
                float4 y1 = *(float4*)&Ys[c][lb+4];
                float yv[8] = {y0.x,y0.y,y0.z,y0.w,y1.x,y1.y,y1.z,y1.w};
                float wr[4] = {wv.x,wv.y,wv.z,wv.w};
                #pragma unroll
                for (int i = 0; i < 8; i++)
                    #pragma unroll
                    for (int j = 0; j < 4; j++) acc[i][j] += yv[i]*wr[j];
            }
        }
    }
    #pragma unroll
    for (int i = 0; i < 8; i++){
        int l = lt + lb + i;
        #pragma unroll
        for (int j = 0; j < 4; j++){
            int o = jb + j;
            if (o < CIN) g_fin[b][o][l] = acc[i][j] + fuseb[o];
        }
    }
}

// ---------------- K7: BatchNorm (stats over B,H,W) + ReLU ----------------
__global__ void __launch_bounds__(256) k_bn(const float* __restrict__ bng, const float* __restrict__ bnb,
                                            float* __restrict__ out){
    int o = blockIdx.x;
    int tid = threadIdx.x;
    __shared__ float ss[256], ss2[256];
    __shared__ float sc, sh;
    float s = 0.f, s2 = 0.f;
    for (int idx = tid; idx < BSZ*LL; idx += 256){
        int b = idx >> 12, l = idx & 4095;
        float v = g_fin[b][o][l];
        s += v; s2 += v*v;
    }
    ss[tid] = s; ss2[tid] = s2; __syncthreads();
    for (int off = 128; off; off >>= 1){
        if (tid < off){ ss[tid] += ss[tid+off]; ss2[tid] += ss2[tid+off]; }
        __syncthreads();
    }
    if (tid == 0){
        float mu  = ss[0]*(1.f/16384.f);
        float var = ss2[0]*(1.f/16384.f) - mu*mu;
        float scale = bng[o]*rsqrtf(var + 1e-5f);
        sc = scale; sh = bnb[o] - mu*scale;
    }
    __syncthreads();
    float scale = sc, shift = sh;
    for (int idx = tid; idx < BSZ*LL; idx += 256){
        int b = idx >> 12, l = idx & 4095;
        float v = g_fin[b][o][l];
        out[((b*CIN)+o)*LL + l] = fmaxf(v*scale + shift, 0.f);
    }
}

// ---------------- launch ----------------
extern "C" void kernel_launch(void* const* d_in, const int* in_sizes, int n_in,
                              void* d_out, int out_size){
    (void)in_sizes; (void)n_in; (void)out_size;
    const float* x         = (const float*)d_in[0];
    const float* f_in_W    = (const float*)d_in[1];
    const float* f_conv_w  = (const float*)d_in[2];
    const float* f_conv_b  = (const float*)d_in[3];
    const float* f_xproj_W = (const float*)d_in[4];
    const float* f_dt_W    = (const float*)d_in[5];
    const float* f_dt_b    = (const float*)d_in[6];
    const float* f_A_log   = (const float*)d_in[7];
    const float* f_D       = (const float*)d_in[8];
    const float* f_out_W   = (const float*)d_in[9];
    const float* b_in_W    = (const float*)d_in[10];
    const float* b_conv_w  = (const float*)d_in[11];
    const float* b_conv_b  = (const float*)d_in[12];
    const float* b_xproj_W = (const float*)d_in[13];
    const float* b_dt_W    = (const float*)d_in[14];
    const float* b_dt_b    = (const float*)d_in[15];
    const float* b_A_log   = (const float*)d_in[16];
    const float* b_D       = (const float*)d_in[17];
    const float* b_out_W   = (const float*)d_in[18];
    const float* fuse_W    = (const float*)d_in[19];
    const float* fuse_b    = (const float*)d_in[20];
    const float* bn_g      = (const float*)d_in[21];
    const float* bn_b      = (const float*)d_in[22];
    float* out = (float*)d_out;

    k_wcomb <<<dim3(DI,2),      128>>>(f_out_W, b_out_W, fuse_W);
    k_inproj<<<dim3(64,3,8),    256>>>(x, f_in_W, b_in_W);
    k_conv  <<<dim3(32,DI,8),   128>>>(f_conv_w, f_conv_b, b_conv_w, b_conv_b);
    k_xproj <<<dim3(16,BSZ,2),  256>>>(f_xproj_W, b_xproj_W);
    k_delta <<<dim3(32,BSZ,2),  256>>>(f_dt_W, f_dt_b, f_D, b_dt_W, b_dt_b, b_D);
    k_scan  <<<dim3(96,BSZ,2),   32>>>(f_A_log, b_A_log);
    k_fuse  <<<dim3(64,BSZ),    256>>>(fuse_b);
    k_bn    <<<CIN,             256>>>(bn_g, bn_b, out);
}

// round 3
// speedup vs baseline: 3.2658x; 3.2658x over previous
#include <cuda_runtime.h>
#include <cstdint>

#define BSZ 4
#define CIN 96
#define LL  4096
#define DI  192
#define NS  16
#define NC  32      // chunks
#define CH  128     // chunk length (NC*CH == LL)

// ---------------- scratch (static device globals; no allocation) ----------------
__device__ float  g_upre[2][BSZ][DI][LL];   // in-proj u part (pre conv)
__device__ float  g_g   [2][BSZ][DI][LL];   // silu(z)
__device__ float  g_u   [2][BSZ][DI][LL];   // post conv+silu u
__device__ float2 g_td  [2][BSZ][DI][LL];   // (delta, delta*u)
__device__ float2 g_gb  [2][BSZ][DI][LL];   // (silu(z), u*D*silu(z))
__device__ float  g_dt6 [2][BSZ][LL][8];    // dt low-rank (6, padded 8)
__device__ float  g_bc  [2][BSZ][LL][2*NS]; // Bm(16) then Cm(16)
__device__ float  g_y   [2][BSZ][DI][LL];   // scan output (gated)
__device__ float  g_fin [BSZ][CIN][LL];     // fused pre-BN output
__device__ float  g_wc  [2][DI][128];       // combined out_W@fuse_W (o padded to 128)
// chunked-scan state
__device__ float  g_P [2][BSZ][DI][NC][NS]; // per-chunk prod(dA)
__device__ float  g_F [2][BSZ][DI][NC][NS]; // per-chunk local final h
__device__ float  g_I [2][BSZ][DI][NC][NS]; // per-chunk initial h (exact)

__device__ __forceinline__ float fsilu(float x){ return x / (1.f + __expf(-x)); }
__device__ __forceinline__ float fex2(float x){ float y; asm("ex2.approx.ftz.f32 %0, %1;" : "=f"(y) : "f"(x)); return y; }

// ---------------- K0: combined projection weights ----------------
__global__ void k_wcomb(const float* __restrict__ foW, const float* __restrict__ boW,
                        const float* __restrict__ fuW){
    int d = blockIdx.x, dir = blockIdx.y;
    int o = threadIdx.x; // 0..127
    float acc = 0.f;
    if (o < CIN){
        const float* oW = dir ? boW : foW;
        #pragma unroll 8
        for (int c = 0; c < CIN; c++)
            acc += oW[d*CIN + c] * fuW[o*(2*CIN) + dir*CIN + c];
    }
    g_wc[dir][d][o] = acc;
}

// ---------------- K1: in-projection GEMM ----------------
__global__ void __launch_bounds__(256) k_inproj(const float* __restrict__ x,
                                                const float* __restrict__ fW,
                                                const float* __restrict__ bW){
    int lt = blockIdx.x*64, jt = blockIdx.y*128;
    int dir = blockIdx.z >> 2, b = blockIdx.z & 3;
    const float* W = dir ? bW : fW;
    __shared__ float Ws[48][128];
    __shared__ float Xs[48][64];
    int tid = threadIdx.x;
    int jb = (tid & 31)*4, lb = (tid >> 5)*8;
    float acc[8][4];
    #pragma unroll
    for (int i = 0; i < 8; i++)
        #pragma unroll
        for (int j = 0; j < 4; j++) acc[i][j] = 0.f;

    for (int cc = 0; cc < 96; cc += 48){
        for (int idx = tid; idx < 48*32; idx += 256){
            int c = idx >> 5, q = idx & 31;
            *(float4*)&Ws[c][q*4] = *(const float4*)&W[(cc+c)*384 + jt + q*4];
        }
        for (int idx = tid; idx < 48*64; idx += 256){
            int c = idx >> 6, i = idx & 63;
            int li = lt + i; if (dir) li = LL-1-li;
            Xs[c][i] = x[((b*CIN)+(cc+c))*LL + li];
        }
        __syncthreads();
        #pragma unroll 4
        for (int c = 0; c < 48; c++){
            float4 wv = *(float4*)&Ws[c][jb];
            float4 x0 = *(float4*)&Xs[c][lb];
            float4 x1 = *(float4*)&Xs[c][lb+4];
            float xv[8] = {x0.x,x0.y,x0.z,x0.w,x1.x,x1.y,x1.z,x1.w};
            float wr[4] = {wv.x,wv.y,wv.z,wv.w};
            #pragma unroll
            for (int i = 0; i < 8; i++)
                #pragma unroll
                for (int j = 0; j < 4; j++) acc[i][j] += xv[i]*wr[j];
        }
        __syncthreads();
    }
    #pragma unroll
    for (int i = 0; i < 8; i++){
        int l = lt + lb + i;
        #pragma unroll
        for (int j = 0; j < 4; j++){
            int jj = jt + jb + j;
            float v = acc[i][j];
            if (jj < DI) g_upre[dir][b][jj][l] = v;
            else         g_g[dir][b][jj-DI][l] = fsilu(v);
        }
    }
}

// ---------------- K2: causal depthwise conv(K=4) + bias + silu ----------------
__global__ void __launch_bounds__(128) k_conv(const float* __restrict__ fw, const float* __restrict__ fb,
                                              const float* __restrict__ bw, const float* __restrict__ bb){
    int dir = blockIdx.z >> 2, b = blockIdx.z & 3;
    int d = blockIdx.y;
    int l = blockIdx.x*128 + threadIdx.x;
    const float* cw = (dir ? bw : fw) + d*4;
    float bias = (dir ? bb : fb)[d];
    const float* up = &g_upre[dir][b][d][0];
    float v = up[l]*cw[3] + bias;
    if (l >= 1) v += up[l-1]*cw[2];
    if (l >= 2) v += up[l-2]*cw[1];
    if (l >= 3) v += up[l-3]*cw[0];
    g_u[dir][b][d][l] = fsilu(v);
}

// ---------------- K3: x-projection GEMM (192 -> 38, padded to 40), L-tile 128 ----------------
__global__ void __launch_bounds__(256) k_xproj(const float* __restrict__ fX, const float* __restrict__ bX){
    int lt = blockIdx.x*128;
    int b = blockIdx.y, dir = blockIdx.z;
    const float* xW = dir ? bX : fX; // (192 x 38)
    __shared__ float Ws[192][40];
    __shared__ float Us[16][128];
    int tid = threadIdx.x;
    for (int idx = tid; idx < 192*40; idx += 256){
        int d = idx/40, j = idx - d*40;
        Ws[d][j] = (j < 38) ? xW[d*38 + j] : 0.f;
    }
    int jb = (tid & 7)*5, lb = (tid >> 3)*4;
    float acc[5][4];
    #pragma unroll
    for (int i = 0; i < 5; i++)
        #pragma unroll
        for (int j = 0; j < 4; j++) acc[i][j] = 0.f;

    for (int c0 = 0; c0 < 192; c0 += 16){
        __syncthreads();
        for (int idx = tid; idx < 16*128; idx += 256){
            int c = idx >> 7, i = idx & 127;
            Us[c][i] = g_u[dir][b][c0+c][lt+i];
        }
        __syncthreads();
        #pragma unroll 4
        for (int c = 0; c < 16; c++){
            float w[5];
            #pragma unroll
            for (int j = 0; j < 5; j++) w[j] = Ws[c0+c][jb+j];
            float4 u0 = *(float4*)&Us[c][lb];
            float uv[4] = {u0.x,u0.y,u0.z,u0.w};
            #pragma unroll
            for (int j = 0; j < 5; j++)
                #pragma unroll
                for (int i = 0; i < 4; i++) acc[j][i] += w[j]*uv[i];
        }
    }
    #pragma unroll
    for (int j = 0; j < 5; j++){
        int jj = jb + j;
        #pragma unroll
        for (int i = 0; i < 4; i++){
            int l = lt + lb + i;
            float v = acc[j][i];
            if (jj < 6)       g_dt6[dir][b][l][jj] = v;
            else if (jj < 38) g_bc[dir][b][l][jj-6] = v;
        }
    }
}

// ---------------- K4: delta = softplus(dt@dt_W + b), pack scan inputs ----------------
__global__ void __launch_bounds__(256) k_delta(const float* __restrict__ fdtW, const float* __restrict__ fdtb,
                                               const float* __restrict__ fD,
                                               const float* __restrict__ bdtW, const float* __restrict__ bdtb,
                                               const float* __restrict__ bD){
    int dir = blockIdx.z, b = blockIdx.y;
    int li = blockIdx.x*128 + (threadIdx.x & 127);
    int du = threadIdx.x >> 7;
    const float* dtW = dir ? bdtW : fdtW;
    const float* dtb = dir ? bdtb : fdtb;
    const float* Dv  = dir ? bD   : fD;
    float dt[6];
    #pragma unroll
    for (int r = 0; r < 6; r++) dt[r] = g_dt6[dir][b][li][r];
    for (int d = du; d < DI; d += 2){
        float acc = dtb[d];
        #pragma unroll
        for (int r = 0; r < 6; r++) acc += dt[r]*dtW[r*DI + d];
        float delta = (acc > 15.f) ? acc : log1pf(__expf(acc));
        float u = g_u[dir][b][d][li];
        float g = g_g[dir][b][d][li];
        g_td[dir][b][d][li] = make_float2(delta, delta*u);
        g_gb[dir][b][d][li] = make_float2(g, u*Dv[d]*g);
    }
}

// ---------------- K5a: chunk-local scan: P = prod dA, F = local final h ----------------
// block = 128 threads = 4 warps = 8 channels; grid = (DI/8, NC, 8)
__global__ void __launch_bounds__(128) k_scan1(const float* __restrict__ fA, const float* __restrict__ bA){
    int tid = threadIdx.x;
    int d = blockIdx.x*8 + (tid >> 4);
    int nc = blockIdx.y;
    int dir = blockIdx.z >> 2, b = blockIdx.z & 3;
    int n = tid & 15;
    const float* Alog = dir ? bA : fA;
    float a2 = -__expf(Alog[d*NS + n]) * 1.4426950408889634f;
    const float2* td = &g_td[dir][b][d][nc*CH];
    const float*  bc = &g_bc[dir][b][nc*CH][0];
    float h = 0.f, P = 1.f;
    #pragma unroll 8
    for (int l = 0; l < CH; l++){
        float2 t = td[l];
        float Bm = bc[l*32 + n];
        float dA = fex2(t.x * a2);
        h = fmaf(dA, h, t.y*Bm);
        P *= dA;
    }
    g_P[dir][b][d][nc][n] = P;
    g_F[dir][b][d][nc][n] = h;
}

// ---------------- K5b: sequential combine across chunks (exact initial states) ----------------
// thread per (dir,b,d,n): 24576 threads
__global__ void __launch_bounds__(256) k_scan2(){
    int idx = blockIdx.x*256 + threadIdx.x; // < 2*BSZ*DI*NS
    int n = idx & 15;
    int d = (idx >> 4) % DI;
    int bb = idx >> 4; bb /= DI;
    int b = bb & 3, dir = bb >> 2;
    float H = 0.f;
    #pragma unroll
    for (int c = 0; c < NC; c++){
        g_I[dir][b][d][c][n] = H;
        H = fmaf(g_P[dir][b][d][c][n], H, g_F[dir][b][d][c][n]);
    }
}

// ---------------- K5c: chunk scan with exact init, emit y ----------------
__global__ void __launch_bounds__(128) k_scan3(const float* __restrict__ fA, const float* __restrict__ bA){
    int tid = threadIdx.x;
    int d = blockIdx.x*8 + (tid >> 4);
    int nc = blockIdx.y;
    int dir = blockIdx.z >> 2, b = blockIdx.z & 3;
    int n = tid & 15;
    const float* Alog = dir ? bA : fA;
    float a2 = -__expf(Alog[d*NS + n]) * 1.4426950408889634f;
    const float2* td = &g_td[dir][b][d][nc*CH];
    const float2* gb = &g_gb[dir][b][d][nc*CH];
    const float*  bc = &g_bc[dir][b][nc*CH][0];
    float* yo = &g_y[dir][b][d][nc*CH];
    float h = g_I[dir][b][d][nc][n];
    #pragma unroll 4
    for (int l = 0; l < CH; l++){
        float2 t = td[l];
        float Bm = bc[l*32 + n];
        float Cm = bc[l*32 + 16 + n];
        float2 G = gb[l];
        float dA = fex2(t.x * a2);
        h = fmaf(dA, h, t.y*Bm);
        float p = h*Cm;
        p += __shfl_xor_sync(0xffffffffu, p, 1);
        p += __shfl_xor_sync(0xffffffffu, p, 2);
        p += __shfl_xor_sync(0xffffffffu, p, 4);
        p += __shfl_xor_sync(0xffffffffu, p, 8);
        if (n == 0) yo[l] = fmaf(p, G.x, G.y);
    }
}

// ---------------- K6: combined out-proj + fuse GEMM ----------------
__global__ void __launch_bounds__(256) k_fuse(const float* __restrict__ fuseb){
    int lt = blockIdx.x*64, b = blockIdx.y;
    __shared__ float Ws[32][128];
    __shared__ float Ys[32][64];
    int tid = threadIdx.x;
    int jb = (tid & 31)*4, lb = (tid >> 5)*8;
    float acc[8][4];
    #pragma unroll
    for (int i = 0; i < 8; i++)
        #pragma unroll
        for (int j = 0; j < 4; j++) acc[i][j] = 0.f;

    for (int dir = 0; dir < 2; dir++){
        for (int c0 = 0; c0 < DI; c0 += 32){
            __syncthreads();
            for (int idx = tid; idx < 32*32; idx += 256){
                int c = idx >> 5, q = idx & 31;
                *(float4*)&Ws[c][q*4] = *(const float4*)&g_wc[dir][c0+c][q*4];
            }
            for (int idx = tid; idx < 32*64; idx += 256){
                int c = idx >> 6, i = idx & 63;
                int li = lt + i; if (dir) li = LL-1-li;
                Ys[c][i] = g_y[dir][b][c0+c][li];
            }
            __syncthreads();
            #pragma unroll 4
            for (int c = 0; c < 32; c++){
                float4 wv = *(float4*)&Ws[c][jb];
                float4 y0 = *(float4*)&Ys[c][lb];
                float4 y1 = *(float4*)&Ys[c][lb+4];
                float yv[8] = {y0.x,y0.y,y0.z,y0.w,y1.x,y1.y,y1.z,y1.w};
                float wr[4] = {wv.x,wv.y,wv.z,wv.w};
                #pragma unroll
                for (int i = 0; i < 8; i++)
                    #pragma unroll
                    for (int j = 0; j < 4; j++) acc[i][j] += yv[i]*wr[j];
            }
        }
    }
    #pragma unroll
    for (int i = 0; i < 8; i++){
        int l = lt + lb + i;
        #pragma unroll
        for (int j = 0; j < 4; j++){
            int o = jb + j;
            if (o < CIN) g_fin[b][o][l] = acc[i][j] + fuseb[o];
        }
    }
}

// ---------------- K7: BatchNorm (stats over B,H,W) + ReLU ----------------
__global__ void __launch_bounds__(256) k_bn(const float* __restrict__ bng, const float* __restrict__ bnb,
                                            float* __restrict__ out){
    int o = blockIdx.x;
    int tid = threadIdx.x;
    __shared__ float ss[256], ss2[256];
    __shared__ float sc, sh;
    float s = 0.f, s2 = 0.f;
    for (int idx = tid; idx < BSZ*LL; idx += 256){
        int b = idx >> 12, l = idx & 4095;
        float v = g_fin[b][o][l];
        s += v; s2 += v*v;
    }
    ss[tid] = s; ss2[tid] = s2; __syncthreads();
    for (int off = 128; off; off >>= 1){
        if (tid < off){ ss[tid] += ss[tid+off]; ss2[tid] += ss2[tid+off]; }
        __syncthreads();
    }
    if (tid == 0){
        float mu  = ss[0]*(1.f/16384.f);
        float var = ss2[0]*(1.f/16384.f) - mu*mu;
        float scale = bng[o]*rsqrtf(var + 1e-5f);
        sc = scale; sh = bnb[o] - mu*scale;
    }
    __syncthreads();
    float scale = sc, shift = sh;
    for (int idx = tid; idx < BSZ*LL; idx += 256){
        int b = idx >> 12, l = idx & 4095;
        float v = g_fin[b][o][l];
        out[((b*CIN)+o)*LL + l] = fmaxf(v*scale + shift, 0.f);
    }
}

// ---------------- launch ----------------
extern "C" void kernel_launch(void* const* d_in, const int* in_sizes, int n_in,
                              void* d_out, int out_size){
    (void)in_sizes; (void)n_in; (void)out_size;
    const float* x         = (const float*)d_in[0];
    const float* f_in_W    = (const float*)d_in[1];
    const float* f_conv_w  = (const float*)d_in[2];
    const float* f_conv_b  = (const float*)d_in[3];
    const float* f_xproj_W = (const float*)d_in[4];
    const float* f_dt_W    = (const float*)d_in[5];
    const float* f_dt_b    = (const float*)d_in[6];
    const float* f_A_log   = (const float*)d_in[7];
    const float* f_D       = (const float*)d_in[8];
    const float* f_out_W   = (const float*)d_in[9];
    const float* b_in_W    = (const float*)d_in[10];
    const float* b_conv_w  = (const float*)d_in[11];
    const float* b_conv_b  = (const float*)d_in[12];
    const float* b_xproj_W = (const float*)d_in[13];
    const float* b_dt_W    = (const float*)d_in[14];
    const float* b_dt_b    = (const float*)d_in[15];
    const float* b_A_log   = (const float*)d_in[16];
    const float* b_D       = (const float*)d_in[17];
    const float* b_out_W   = (const float*)d_in[18];
    const float* fuse_W    = (const float*)d_in[19];
    const float* fuse_b    = (const float*)d_in[20];
    const float* bn_g      = (const float*)d_in[21];
    const float* bn_b      = (const float*)d_in[22];
    float* out = (float*)d_out;

    k_wcomb <<<dim3(DI,2),       128>>>(f_out_W, b_out_W, fuse_W);
    k_inproj<<<dim3(64,3,8),     256>>>(x, f_in_W, b_in_W);
    k_conv  <<<dim3(32,DI,8),    128>>>(f_conv_w, f_conv_b, b_conv_w, b_conv_b);
    k_xproj <<<dim3(32,BSZ,2),   256>>>(f_xproj_W, b_xproj_W);
    k_delta <<<dim3(32,BSZ,2),   256>>>(f_dt_W, f_dt_b, f_D, b_dt_W, b_dt_b, b_D);
    k_scan1 <<<dim3(DI/8,NC,8),  128>>>(f_A_log, b_A_log);
    k_scan2 <<<96,               256>>>();
    k_scan3 <<<dim3(DI/8,NC,8),  128>>>(f_A_log, b_A_log);
    k_fuse  <<<dim3(64,BSZ),     256>>>(fuse_b);
    k_bn    <<<CIN,              256>>>(bn_g, bn_b, out);
}

// round 4
// speedup vs baseline: 3.3252x; 1.0182x over previous
#include <cuda_runtime.h>
#include <cstdint>

#define BSZ 4
#define CIN 96
#define LL  4096
#define DI  192
#define NS  16
#define NC  32      // chunks
#define CH  128     // chunk length (NC*CH == LL)

// ---------------- scratch (static device globals; no allocation) ----------------
__device__ float  g_upre[2][BSZ][DI][LL];   // in-proj u part (pre conv)
__device__ float  g_g   [2][BSZ][DI][LL];   // silu(z)
__device__ float  g_u   [2][BSZ][DI][LL];   // post conv+silu u
__device__ float2 g_td  [2][BSZ][DI][LL];   // (delta, delta*u)
__device__ float2 g_gb  [2][BSZ][DI][LL];   // (silu(z), u*D*silu(z))
__device__ float  g_dt6 [2][BSZ][LL][8];    // dt low-rank (6, padded 8)
__device__ float  g_bc  [2][BSZ][LL][2*NS]; // Bm(16) then Cm(16)
__device__ float  g_y   [2][BSZ][DI][LL];   // scan output (gated)
__device__ float  g_fin [BSZ][CIN][LL];     // fused pre-BN output
__device__ float  g_wc  [2][DI][128];       // combined out_W@fuse_W (o padded to 128)
// chunked-scan state
__device__ float  g_P [2][BSZ][DI][NC][NS]; // per-chunk prod(dA)
__device__ float  g_F [2][BSZ][DI][NC][NS]; // per-chunk local final h
__device__ float  g_I [2][BSZ][DI][NC][NS]; // per-chunk initial h (exact)

__device__ __forceinline__ float fsilu(float x){ return x / (1.f + __expf(-x)); }
__device__ __forceinline__ float fex2(float x){ float y; asm("ex2.approx.ftz.f32 %0, %1;" : "=f"(y) : "f"(x)); return y; }

// ---------------- K0: combined projection weights ----------------
__global__ void k_wcomb(const float* __restrict__ foW, const float* __restrict__ boW,
                        const float* __restrict__ fuW){
    int d = blockIdx.x, dir = blockIdx.y;
    int o = threadIdx.x; // 0..127
    float acc = 0.f;
    if (o < CIN){
        const float* oW = dir ? boW : foW;
        #pragma unroll 8
        for (int c = 0; c < CIN; c++)
            acc += oW[d*CIN + c] * fuW[o*(2*CIN) + dir*CIN + c];
    }
    g_wc[dir][d][o] = acc;
}

// ---------------- K1: in-projection GEMM ----------------
__global__ void __launch_bounds__(256) k_inproj(const float* __restrict__ x,
                                                const float* __restrict__ fW,
                                                const float* __restrict__ bW){
    int lt = blockIdx.x*64, jt = blockIdx.y*128;
    int dir = blockIdx.z >> 2, b = blockIdx.z & 3;
    const float* W = dir ? bW : fW;
    __shared__ float Ws[48][128];
    __shared__ float Xs[48][64];
    int tid = threadIdx.x;
    int jb = (tid & 31)*4, lb = (tid >> 5)*8;
    float acc[8][4];
    #pragma unroll
    for (int i = 0; i < 8; i++)
        #pragma unroll
        for (int j = 0; j < 4; j++) acc[i][j] = 0.f;

    for (int cc = 0; cc < 96; cc += 48){
        for (int idx = tid; idx < 48*32; idx += 256){
            int c = idx >> 5, q = idx & 31;
            *(float4*)&Ws[c][q*4] = *(const float4*)&W[(cc+c)*384 + jt + q*4];
        }
        for (int idx = tid; idx < 48*64; idx += 256){
            int c = idx >> 6, i = idx & 63;
            int li = lt + i; if (dir) li = LL-1-li;
            Xs[c][i] = x[((b*CIN)+(cc+c))*LL + li];
        }
        __syncthreads();
        #pragma unroll 4
        for (int c = 0; c < 48; c++){
            float4 wv = *(float4*)&Ws[c][jb];
            float4 x0 = *(float4*)&Xs[c][lb];
            float4 x1 = *(float4*)&Xs[c][lb+4];
            float xv[8] = {x0.x,x0.y,x0.z,x0.w,x1.x,x1.y,x1.z,x1.w};
            float wr[4] = {wv.x,wv.y,wv.z,wv.w};
            #pragma unroll
            for (int i = 0; i < 8; i++)
                #pragma unroll
                for (int j = 0; j < 4; j++) acc[i][j] += xv[i]*wr[j];
        }
        __syncthreads();
    }
    #pragma unroll
    for (int i = 0; i < 8; i++){
        int l = lt + lb + i;
        #pragma unroll
        for (int j = 0; j < 4; j++){
            int jj = jt + jb + j;
            float v = acc[i][j];
            if (jj < DI) g_upre[dir][b][jj][l] = v;
            else         g_g[dir][b][jj-DI][l] = fsilu(v);
        }
    }
}

// ---------------- K2: causal depthwise conv(K=4) + bias + silu ----------------
__global__ void __launch_bounds__(128) k_conv(const float* __restrict__ fw, const float* __restrict__ fb,
                                              const float* __restrict__ bw, const float* __restrict__ bb){
    int dir = blockIdx.z >> 2, b = blockIdx.z & 3;
    int d = blockIdx.y;
    int l = blockIdx.x*128 + threadIdx.x;
    const float* cw = (dir ? bw : fw) + d*4;
    float bias = (dir ? bb : fb)[d];
    const float* up = &g_upre[dir][b][d][0];
    float v = up[l]*cw[3] + bias;
    if (l >= 1) v += up[l-1]*cw[2];
    if (l >= 2) v += up[l-2]*cw[1];
    if (l >= 3) v += up[l-3]*cw[0];
    g_u[dir][b][d][l] = fsilu(v);
}

// ---------------- K3: x-projection GEMM (192 -> 38, padded to 40), L-tile 128 ----------------
__global__ void __launch_bounds__(256) k_xproj(const float* __restrict__ fX, const float* __restrict__ bX){
    int lt = blockIdx.x*128;
    int b = blockIdx.y, dir = blockIdx.z;
    const float* xW = dir ? bX : fX; // (192 x 38)
    __shared__ float Ws[192][40];
    __shared__ float Us[16][128];
    int tid = threadIdx.x;
    for (int idx = tid; idx < 192*40; idx += 256){
        int d = idx/40, j = idx - d*40;
        Ws[d][j] = (j < 38) ? xW[d*38 + j] : 0.f;
    }
    int jb = (tid & 7)*5, lb = (tid >> 3)*4;
    float acc[5][4];
    #pragma unroll
    for (int i = 0; i < 5; i++)
        #pragma unroll
        for (int j = 0; j < 4; j++) acc[i][j] = 0.f;

    for (int c0 = 0; c0 < 192; c0 += 16){
        __syncthreads();
        for (int idx = tid; idx < 16*128; idx += 256){
            int c = idx >> 7, i = idx & 127;
            Us[c][i] = g_u[dir][b][c0+c][lt+i];
        }
        __syncthreads();
        #pragma unroll 4
        for (int c = 0; c < 16; c++){
            float w[5];
            #pragma unroll
            for (int j = 0; j < 5; j++) w[j] = Ws[c0+c][jb+j];
            float4 u0 = *(float4*)&Us[c][lb];
            float uv[4] = {u0.x,u0.y,u0.z,u0.w};
            #pragma unroll
            for (int j = 0; j < 5; j++)
                #pragma unroll
                for (int i = 0; i < 4; i++) acc[j][i] += w[j]*uv[i];
        }
    }
    #pragma unroll
    for (int j = 0; j < 5; j++){
        int jj = jb + j;
        #pragma unroll
        for (int i = 0; i < 4; i++){
            int l = lt + lb + i;
            float v = acc[j][i];
            if (jj < 6)       g_dt6[dir][b][l][jj] = v;
            else if (jj < 38) g_bc[dir][b][l][jj-6] = v;
        }
    }
}

// ---------------- K4: delta = softplus(dt@dt_W + b), pack scan inputs ----------------
__global__ void __launch_bounds__(256) k_delta(const float* __restrict__ fdtW, const float* __restrict__ fdtb,
                                               const float* __restrict__ fD,
                                               const float* __restrict__ bdtW, const float* __restrict__ bdtb,
                                               const float* __restrict__ bD){
    int dir = blockIdx.z, b = blockIdx.y;
    int li = blockIdx.x*128 + (threadIdx.x & 127);
    int du = threadIdx.x >> 7;
    const float* dtW = dir ? bdtW : fdtW;
    const float* dtb = dir ? bdtb : fdtb;
    const float* Dv  = dir ? bD   : fD;
    float dt[6];
    #pragma unroll
    for (int r = 0; r < 6; r++) dt[r] = g_dt6[dir][b][li][r];
    for (int d = du; d < DI; d += 2){
        float acc = dtb[d];
        #pragma unroll
        for (int r = 0; r < 6; r++) acc += dt[r]*dtW[r*DI + d];
        float delta = (acc > 15.f) ? acc : log1pf(__expf(acc));
        float u = g_u[dir][b][d][li];
        float g = g_g[dir][b][d][li];
        g_td[dir][b][d][li] = make_float2(delta, delta*u);
        g_gb[dir][b][d][li] = make_float2(g, u*Dv[d]*g);
    }
}

// ---------------- K5a: chunk-local scan: P = prod dA, F = local final h ----------------
// block = 128 threads = 4 warps = 8 channels; grid = (DI/8, NC, 8)
__global__ void __launch_bounds__(128) k_scan1(const float* __restrict__ fA, const float* __restrict__ bA){
    int tid = threadIdx.x;
    int d = blockIdx.x*8 + (tid >> 4);
    int nc = blockIdx.y;
    int dir = blockIdx.z >> 2, b = blockIdx.z & 3;
    int n = tid & 15;
    const float* Alog = dir ? bA : fA;
    float a2 = -__expf(Alog[d*NS + n]) * 1.4426950408889634f;
    const float2* td = &g_td[dir][b][d][nc*CH];
    const float*  bc = &g_bc[dir][b][nc*CH][0];
    float h = 0.f, P = 1.f;
    #pragma unroll 8
    for (int l = 0; l < CH; l++){
        float2 t = td[l];
        float Bm = bc[l*32 + n];
        float dA = fex2(t.x * a2);
        h = fmaf(dA, h, t.y*Bm);
        P *= dA;
    }
    g_P[dir][b][d][nc][n] = P;
    g_F[dir][b][d][nc][n] = h;
}

// ---------------- K5b: sequential combine across chunks (exact initial states) ----------------
// thread per (dir,b,d,n): 24576 threads
__global__ void __launch_bounds__(256) k_scan2(){
    int idx = blockIdx.x*256 + threadIdx.x; // < 2*BSZ*DI*NS
    int n = idx & 15;
    int d = (idx >> 4) % DI;
    int bb = idx >> 4; bb /= DI;
    int b = bb & 3, dir = bb >> 2;
    float H = 0.f;
    #pragma unroll
    for (int c = 0; c < NC; c++){
        g_I[dir][b][d][c][n] = H;
        H = fmaf(g_P[dir][b][d][c][n], H, g_F[dir][b][d][c][n]);
    }
}

// ---------------- K5c: chunk scan with exact init, emit y ----------------
__global__ void __launch_bounds__(128) k_scan3(const float* __restrict__ fA, const float* __restrict__ bA){
    int tid = threadIdx.x;
    int d = blockIdx.x*8 + (tid >> 4);
    int nc = blockIdx.y;
    int dir = blockIdx.z >> 2, b = blockIdx.z & 3;
    int n = tid & 15;
    const float* Alog = dir ? bA : fA;
    float a2 = -__expf(Alog[d*NS + n]) * 1.4426950408889634f;
    const float2* td = &g_td[dir][b][d][nc*CH];
    const float2* gb = &g_gb[dir][b][d][nc*CH];
    const float*  bc = &g_bc[dir][b][nc*CH][0];
    float* yo = &g_y[dir][b][d][nc*CH];
    float h = g_I[dir][b][d][nc][n];
    #pragma unroll 4
    for (int l = 0; l < CH; l++){
        float2 t = td[l];
        float Bm = bc[l*32 + n];
        float Cm = bc[l*32 + 16 + n];
        float2 G = gb[l];
        float dA = fex2(t.x * a2);
        h = fmaf(dA, h, t.y*Bm);
        float p = h*Cm;
        p += __shfl_xor_sync(0xffffffffu, p, 1);
        p += __shfl_xor_sync(0xffffffffu, p, 2);
        p += __shfl_xor_sync(0xffffffffu, p, 4);
        p += __shfl_xor_sync(0xffffffffu, p, 8);
        if (n == 0) yo[l] = fmaf(p, G.x, G.y);
    }
}

// ---------------- K6: combined out-proj + fuse GEMM ----------------
__global__ void __launch_bounds__(256) k_fuse(const float* __restrict__ fuseb){
    int lt = blockIdx.x*64, b = blockIdx.y;
    __shared__ float Ws[32][128];
    __shared__ float Ys[32][64];
    int tid = threadIdx.x;
    int jb = (tid & 31)*4, lb = (tid >> 5)*8;
    float acc[8][4];
    #pragma unroll
    for (int i = 0; i < 8; i++)
        #pragma unroll
        for (int j = 0; j < 4; j++) acc[i][j] = 0.f;

    for (int dir = 0; dir < 2; dir++){
        for (int c0 = 0; c0 < DI; c0 += 32){
            __syncthreads();
            for (int idx = tid; idx < 32*32; idx += 256){
                int c = idx >> 5, q = idx & 31;
                *(float4*)&Ws[c][q*4] = *(const float4*)&g_wc[dir][c0+c][q*4];
            }
            for (int idx = tid; idx < 32*64; idx += 256){
                int c = idx >> 6, i = idx & 63;
                int li = lt + i; if (dir) li = LL-1-li;
                Ys[c][i] = g_y[dir][b][c0+c][li];
            }
            __syncthreads();
            #pragma unroll 4
            for (int c = 0; c < 32; c++){
                float4 wv = *(float4*)&Ws[c][jb];
                float4 y0 = *(float4*)&Ys[c][lb];
                float4 y1 = *(float4*)&Ys[c][lb+4];
                float yv[8] = {y0.x,y0.y,y0.z,y0.w,y1.x,y1.y,y1.z,y1.w};
                float wr[4] = {wv.x,wv.y,wv.z,wv.w};
                #pragma unroll
                for (int i = 0; i < 8; i++)
                    #pragma unroll
                    for (int j = 0; j < 4; j++) acc[i][j] += yv[i]*wr[j];
            }
        }
    }
    #pragma unroll
    for (int i = 0; i < 8; i++){
        int l = lt + lb + i;
        #pragma unroll
        for (int j = 0; j < 4; j++){
            int o = jb + j;
            if (o < CIN) g_fin[b][o][l] = acc[i][j] + fuseb[o];
        }
    }
}

// ---------------- K7: BatchNorm (stats over B,H,W) + ReLU ----------------
__global__ void __launch_bounds__(256) k_bn(const float* __restrict__ bng, const float* __restrict__ bnb,
                                            float* __restrict__ out){
    int o = blockIdx.x;
    int tid = threadIdx.x;
    __shared__ float ss[256], ss2[256];
    __shared__ float sc, sh;
    float s = 0.f, s2 = 0.f;
    for (int idx = tid; idx < BSZ*LL; idx += 256){
        int b = idx >> 12, l = idx & 4095;
        float v = g_fin[b][o][l];
        s += v; s2 += v*v;
    }
    ss[tid] = s; ss2[tid] = s2; __syncthreads();
    for (int off = 128; off; off >>= 1){
        if (tid < off){ ss[tid] += ss[tid+off]; ss2[tid] += ss2[tid+off]; }
        __syncthreads();
    }
    if (tid == 0){
        float mu  = ss[0]*(1.f/16384.f);
        float var = ss2[0]*(1.f/16384.f) - mu*mu;
        float scale = bng[o]*rsqrtf(var + 1e-5f);
        sc = scale; sh = bnb[o] - mu*scale;
    }
    __syncthreads();
    float scale = sc, shift = sh;
    for (int idx = tid; idx < BSZ*LL; idx += 256){
        int b = idx >> 12, l = idx & 4095;
        float v = g_fin[b][o][l];
        out[((b*CIN)+o)*LL + l] = fmaxf(v*scale + shift, 0.f);
    }
}

// ---------------- launch ----------------
extern "C" void kernel_launch(void* const* d_in, const int* in_sizes, int n_in,
                              void* d_out, int out_size){
    (void)in_sizes; (void)n_in; (void)out_size;
    const float* x         = (const float*)d_in[0];
    const float* f_in_W    = (const float*)d_in[1];
    const float* f_conv_w  = (const float*)d_in[2];
    const float* f_conv_b  = (const float*)d_in[3];
    const float* f_xproj_W = (const float*)d_in[4];
    const float* f_dt_W    = (const float*)d_in[5];
    const float* f_dt_b    = (const float*)d_in[6];
    const float* f_A_log   = (const float*)d_in[7];
    const float* f_D       = (const float*)d_in[8];
    const float* f_out_W   = (const float*)d_in[9];
    const float* b_in_W    = (const float*)d_in[10];
    const float* b_conv_w  = (const float*)d_in[11];
    const float* b_conv_b  = (const float*)d_in[12];
    const float* b_xproj_W = (const float*)d_in[13];
    const float* b_dt_W    = (const float*)d_in[14];
    const float* b_dt_b    = (const float*)d_in[15];
    const float* b_A_log   = (const float*)d_in[16];
    const float* b_D       = (const float*)d_in[17];
    const float* b_out_W   = (const float*)d_in[18];
    const float* fuse_W    = (const float*)d_in[19];
    const float* fuse_b    = (const float*)d_in[20];
    const float* bn_g      = (const float*)d_in[21];
    const float* bn_b      = (const float*)d_in[22];
    float* out = (float*)d_out;

    k_wcomb <<<dim3(DI,2),       128>>>(f_out_W, b_out_W, fuse_W);
    k_inproj<<<dim3(64,3,8),     256>>>(x, f_in_W, b_in_W);
    k_conv  <<<dim3(32,DI,8),    128>>>(f_conv_w, f_conv_b, b_conv_w, b_conv_b);
    k_xproj <<<dim3(32,BSZ,2),   256>>>(f_xproj_W, b_xproj_W);
    k_delta <<<dim3(32,BSZ,2),   256>>>(f_dt_W, f_dt_b, f_D, b_dt_W, b_dt_b, b_D);
    k_scan1 <<<dim3(DI/8,NC,8),  128>>>(f_A_log, b_A_log);
    k_scan2 <<<96,               256>>>();
    k_scan3 <<<dim3(DI/8,NC,8),  128>>>(f_A_log, b_A_log);
    k_fuse  <<<dim3(64,BSZ),     256>>>(fuse_b);
    k_bn    <<<CIN,              256>>>(bn_g, bn_b, out);
}